// round 3
// baseline (speedup 1.0000x reference)
#include <cuda_runtime.h>
#include <stdint.h>

#define KG_MAX 200000
#define B_MAX  20000
#define E_MAX  640000
#define IN_DIM 256
#define OUT_DIM 128

// ---------------- device scratch ----------------
__device__ int   g_is64;
__device__ __align__(16) float g_vL[IN_DIM];
__device__ __align__(16) float g_vR[IN_DIM];
__device__ float g_cLR;
__device__ float g_dR[KG_MAX];                 // ent[v] . vR
__device__ float g_sL[B_MAX];                  // ent[bid[r]] . vL + cLR
__device__ int   g_cnt[B_MAX];
__device__ int   g_cur[B_MAX];
__device__ int   g_off[B_MAX + 1];
__device__ int   g_csr[E_MAX];
__device__ __align__(16) float g_Wt[IN_DIM * OUT_DIM];       // [k][n]
__device__ __align__(16) float g_Y[(size_t)B_MAX * IN_DIM];  // [B,256]

__device__ __forceinline__ int ld_row(const void* p, int e, int is64) {
    return is64 ? (int)((const long long*)p)[e] : ((const int*)p)[e];
}
__device__ __forceinline__ int ld_col(const void* p, int E, int e, int is64) {
    return is64 ? (int)((const long long*)p)[(long long)E + e]
                : ((const int*)p)[E + e];
}

// ---------------- k_prep ----------------
__global__ void k_prep(const void* __restrict__ bids,
                       const float* __restrict__ W,
                       const float* __restrict__ bias,
                       const float* __restrict__ wa,
                       int B) {
    int t = threadIdx.x;  // 256
    __shared__ int s_nz;
    if (t == 0) s_nz = 0;
    __syncthreads();
    const unsigned int* u = (const unsigned int*)bids;
    if (u[2 * t + 1] != 0u) atomicOr(&s_nz, 1);
    __syncthreads();
    if (t == 0) g_is64 = s_nz ? 0 : 1;

    float vl = 0.f, vr = 0.f;
#pragma unroll 4
    for (int n = 0; n < OUT_DIM; n++) {
        float w = W[n * IN_DIM + t];
        vl = fmaf(w, wa[n], vl);
        vr = fmaf(w, wa[OUT_DIM + n], vr);
    }
    g_vL[t] = vl;
    g_vR[t] = vr;

    __shared__ float sr[256];
    sr[t] = (t < OUT_DIM) ? bias[t] * (wa[t] + wa[t + OUT_DIM]) : 0.f;
    __syncthreads();
    for (int off = 128; off > 0; off >>= 1) {
        if (t < off) sr[t] += sr[t + off];
        __syncthreads();
    }
    if (t == 0) g_cLR = sr[0];

    for (int idx = t; idx < OUT_DIM * IN_DIM; idx += 256) {
        int k = idx >> 7, n = idx & 127;
        g_Wt[idx] = W[n * IN_DIM + k];
    }
    for (int i = t; i < B; i += 256) { g_cnt[i] = 0; g_cur[i] = 0; }
}

// ---------------- k_fused: dR stream + sL gather + degree histogram --------
__global__ void __launch_bounds__(256) k_fused(
        const float* __restrict__ ent, const void* __restrict__ bids,
        const void* __restrict__ ei, int KG, int B, int E,
        int nbdr, int nbsl) {
    int bid = blockIdx.x;
    int t = threadIdx.x, w = t >> 5, lane = t & 31;
    if (bid < nbdr) {
        int v = bid * 8 + w;
        if (v < KG) {
            const float* x = ent + (size_t)v * IN_DIM + lane * 8;
            float4 x0 = *(const float4*)x;
            float4 x1 = *(const float4*)(x + 4);
            float4 r0 = *(const float4*)&g_vR[lane * 8];
            float4 r1 = *(const float4*)&g_vR[lane * 8 + 4];
            float d = x0.x * r0.x + x0.y * r0.y + x0.z * r0.z + x0.w * r0.w
                    + x1.x * r1.x + x1.y * r1.y + x1.z * r1.z + x1.w * r1.w;
#pragma unroll
            for (int o = 16; o > 0; o >>= 1)
                d += __shfl_xor_sync(0xffffffffu, d, o);
            if (lane == 0) g_dR[v] = d;
        }
    } else if (bid < nbdr + nbsl) {
        int r = (bid - nbdr) * 8 + w;
        if (r < B) {
            long long gi = g_is64 ? ((const long long*)bids)[r]
                                  : (long long)((const int*)bids)[r];
            const float* x = ent + gi * (long long)IN_DIM + lane * 8;
            float4 x0 = *(const float4*)x;
            float4 x1 = *(const float4*)(x + 4);
            float4 l0 = *(const float4*)&g_vL[lane * 8];
            float4 l1 = *(const float4*)&g_vL[lane * 8 + 4];
            float d = x0.x * l0.x + x0.y * l0.y + x0.z * l0.z + x0.w * l0.w
                    + x1.x * l1.x + x1.y * l1.y + x1.z * l1.z + x1.w * l1.w;
#pragma unroll
            for (int o = 16; o > 0; o >>= 1)
                d += __shfl_xor_sync(0xffffffffu, d, o);
            if (lane == 0) g_sL[r] = d + g_cLR;
        }
    } else {
        int e = (bid - nbdr - nbsl) * 256 + t;
        if (e < E) {
            int r = ld_row(ei, e, g_is64);
            atomicAdd(&g_cnt[r], 1);
        }
    }
}

// ---------------- k_scan ----------------
__global__ void k_scan(int B) {
    __shared__ int s[1024];
    int t = threadIdx.x;
    int CH = (B + 1023) >> 10;
    int lo = t * CH, hi = min(lo + CH, B);
    int sum = 0;
    for (int i = lo; i < hi; i++) sum += g_cnt[i];
    s[t] = sum;
    __syncthreads();
    for (int off = 1; off < 1024; off <<= 1) {
        int v = (t >= off) ? s[t - off] : 0;
        __syncthreads();
        s[t] += v;
        __syncthreads();
    }
    int run = (t == 0) ? 0 : s[t - 1];
    for (int i = lo; i < hi; i++) { g_off[i] = run; run += g_cnt[i]; }
    if (t == 1023) g_off[B] = s[1023];
}

// ---------------- k_scatter ----------------
__global__ void k_scatter(const void* __restrict__ ei, int E) {
    int e = blockIdx.x * blockDim.x + threadIdx.x;
    if (e >= E) return;
    int r = ld_row(ei, e, g_is64);
    int pos = atomicAdd(&g_cur[r], 1);
    g_csr[g_off[r] + pos] = e;
}

// ---------------- k_agg: warp per row, MLP-staged gather ----------------
// Phase 1: bitonic-sort edge ids (determinism). Phase 2: compute col+att
// for all edges into shared. Phase 3: gather-accumulate, 4 edges per step
// with all 8 LDG.128 issued before any FMA (MLP=8 per warp).
__global__ void __launch_bounds__(256) k_agg(const float* __restrict__ ent,
                                             const void* __restrict__ ei,
                                             int E, int B) {
    __shared__ int   s_e[8][128];   // edge ids, then overwritten with cols
    __shared__ float s_a[8][128];   // att per edge
    int t = threadIdx.x, w = t >> 5, lane = t & 31;
    int r = blockIdx.x * 8 + w;
    if (r >= B) return;
    int is64 = g_is64;
    int off0 = g_off[r];
    int deg = g_off[r + 1] - off0;
    float base = g_sL[r];

    const float* entl = ent + lane * 8;
    float4 A0 = make_float4(0.f, 0.f, 0.f, 0.f);
    float4 A1 = make_float4(0.f, 0.f, 0.f, 0.f);
    float asum = 0.f;

    if (deg <= 128) {
        int P = 1;
        while (P < deg) P <<= 1;
        for (int i = lane; i < P; i += 32)
            s_e[w][i] = (i < deg) ? g_csr[off0 + i] : 0x7fffffff;
        __syncwarp();
        for (int k = 2; k <= P; k <<= 1) {
            for (int j = k >> 1; j > 0; j >>= 1) {
                for (int i = lane; i < P; i += 32) {
                    int ixj = i ^ j;
                    if (ixj > i) {
                        int a = s_e[w][i], c = s_e[w][ixj];
                        bool up = ((i & k) == 0);
                        if ((a > c) == up) { s_e[w][i] = c; s_e[w][ixj] = a; }
                    }
                }
                __syncwarp();
            }
        }
        // col + att pass (overwrites s_e with cols)
        for (int i = lane; i < deg; i += 32) {
            int e = s_e[w][i];
            int c = ld_col(ei, E, e, is64);
            float s = base + g_dR[c];
            float v = s >= 0.f ? s : 0.2f * s;
            s_e[w][i] = c;
            s_a[w][i] = __expf(-v);
        }
        __syncwarp();

        int i = 0;
        for (; i + 4 <= deg; i += 4) {
            int c0 = s_e[w][i],     c1 = s_e[w][i + 1];
            int c2 = s_e[w][i + 2], c3 = s_e[w][i + 3];
            float a0 = s_a[w][i],     a1 = s_a[w][i + 1];
            float a2 = s_a[w][i + 2], a3 = s_a[w][i + 3];
            const float* p0 = entl + (size_t)c0 * IN_DIM;
            const float* p1 = entl + (size_t)c1 * IN_DIM;
            const float* p2 = entl + (size_t)c2 * IN_DIM;
            const float* p3 = entl + (size_t)c3 * IN_DIM;
            float4 x00 = *(const float4*)p0, x01 = *(const float4*)(p0 + 4);
            float4 x10 = *(const float4*)p1, x11 = *(const float4*)(p1 + 4);
            float4 x20 = *(const float4*)p2, x21 = *(const float4*)(p2 + 4);
            float4 x30 = *(const float4*)p3, x31 = *(const float4*)(p3 + 4);
            // accumulate strictly in edge order (determinism)
            asum += a0;
            A0.x = fmaf(a0, x00.x, A0.x); A0.y = fmaf(a0, x00.y, A0.y);
            A0.z = fmaf(a0, x00.z, A0.z); A0.w = fmaf(a0, x00.w, A0.w);
            A1.x = fmaf(a0, x01.x, A1.x); A1.y = fmaf(a0, x01.y, A1.y);
            A1.z = fmaf(a0, x01.z, A1.z); A1.w = fmaf(a0, x01.w, A1.w);
            asum += a1;
            A0.x = fmaf(a1, x10.x, A0.x); A0.y = fmaf(a1, x10.y, A0.y);
            A0.z = fmaf(a1, x10.z, A0.z); A0.w = fmaf(a1, x10.w, A0.w);
            A1.x = fmaf(a1, x11.x, A1.x); A1.y = fmaf(a1, x11.y, A1.y);
            A1.z = fmaf(a1, x11.z, A1.z); A1.w = fmaf(a1, x11.w, A1.w);
            asum += a2;
            A0.x = fmaf(a2, x20.x, A0.x); A0.y = fmaf(a2, x20.y, A0.y);
            A0.z = fmaf(a2, x20.z, A0.z); A0.w = fmaf(a2, x20.w, A0.w);
            A1.x = fmaf(a2, x21.x, A1.x); A1.y = fmaf(a2, x21.y, A1.y);
            A1.z = fmaf(a2, x21.z, A1.z); A1.w = fmaf(a2, x21.w, A1.w);
            asum += a3;
            A0.x = fmaf(a3, x30.x, A0.x); A0.y = fmaf(a3, x30.y, A0.y);
            A0.z = fmaf(a3, x30.z, A0.z); A0.w = fmaf(a3, x30.w, A0.w);
            A1.x = fmaf(a3, x31.x, A1.x); A1.y = fmaf(a3, x31.y, A1.y);
            A1.z = fmaf(a3, x31.z, A1.z); A1.w = fmaf(a3, x31.w, A1.w);
        }
        for (; i < deg; i++) {
            int c = s_e[w][i];
            float a = s_a[w][i];
            const float* p = entl + (size_t)c * IN_DIM;
            float4 x0 = *(const float4*)p, x1 = *(const float4*)(p + 4);
            asum += a;
            A0.x = fmaf(a, x0.x, A0.x); A0.y = fmaf(a, x0.y, A0.y);
            A0.z = fmaf(a, x0.z, A0.z); A0.w = fmaf(a, x0.w, A0.w);
            A1.x = fmaf(a, x1.x, A1.x); A1.y = fmaf(a, x1.y, A1.y);
            A1.z = fmaf(a, x1.z, A1.z); A1.w = fmaf(a, x1.w, A1.w);
        }
    } else {
        // deterministic fallback: increasing edge-id selection (rare)
        int last = -1;
        for (int rk = 0; rk < deg; rk++) {
            int m = 0x7fffffff;
            for (int i = lane; i < deg; i += 32) {
                int ec = g_csr[off0 + i];
                if (ec > last && ec < m) m = ec;
            }
#pragma unroll
            for (int o = 16; o > 0; o >>= 1)
                m = min(m, __shfl_xor_sync(0xffffffffu, m, o));
            int c = ld_col(ei, E, m, is64);
            float s = base + g_dR[c];
            float v = s >= 0.f ? s : 0.2f * s;
            float a = __expf(-v);
            const float* x = entl + (size_t)c * IN_DIM;
            float4 x0 = *(const float4*)x;
            float4 x1 = *(const float4*)(x + 4);
            asum += a;
            A0.x = fmaf(a, x0.x, A0.x); A0.y = fmaf(a, x0.y, A0.y);
            A0.z = fmaf(a, x0.z, A0.z); A0.w = fmaf(a, x0.w, A0.w);
            A1.x = fmaf(a, x1.x, A1.x); A1.y = fmaf(a, x1.y, A1.y);
            A1.z = fmaf(a, x1.z, A1.z); A1.w = fmaf(a, x1.w, A1.w);
            last = m;
        }
    }

    float inv = 1.0f / asum;
    float* y = &g_Y[(size_t)r * IN_DIM + lane * 8];
    float4 o0, o1;
    o0.x = A0.x * inv; o0.y = A0.y * inv; o0.z = A0.z * inv; o0.w = A0.w * inv;
    o1.x = A1.x * inv; o1.y = A1.y * inv; o1.z = A1.z * inv; o1.w = A1.w * inv;
    *(float4*)y = o0;
    *(float4*)(y + 4) = o1;
}

// ---------------- k_gemm: out = prelu(Y @ Wt + b), 128x128x16 tile, 8x8 ----
__global__ void __launch_bounds__(256) k_gemm(const float* __restrict__ bias,
                                              const float* __restrict__ prelu,
                                              float* __restrict__ out, int M) {
    const int BK = 16;
    __shared__ __align__(16) float Ys[BK][128];
    __shared__ __align__(16) float Ws[BK][128];

    int tid = threadIdx.x;
    int m0 = blockIdx.x * 128;
    int tm = tid >> 4;
    int tn = tid & 15;

    float acc[8][8];
#pragma unroll
    for (int i = 0; i < 8; i++)
#pragma unroll
        for (int j = 0; j < 8; j++) acc[i][j] = 0.f;

    for (int kt = 0; kt < IN_DIM; kt += BK) {
#pragma unroll
        for (int i = 0; i < 2; i++) {
            int f = tid * 2 + i;
            int mr = f >> 2;
            int kc = (f & 3) << 2;
            float4 v = make_float4(0.f, 0.f, 0.f, 0.f);
            int row = m0 + mr;
            if (row < M) v = *(const float4*)&g_Y[(size_t)row * IN_DIM + kt + kc];
            Ys[kc + 0][mr] = v.x; Ys[kc + 1][mr] = v.y;
            Ys[kc + 2][mr] = v.z; Ys[kc + 3][mr] = v.w;
        }
#pragma unroll
        for (int i = 0; i < 2; i++) {
            int idx = tid + i * 256;
            int kr = idx >> 5;
            int nc = (idx & 31) << 2;
            *(float4*)&Ws[kr][nc] = *(const float4*)&g_Wt[(kt + kr) * OUT_DIM + nc];
        }
        __syncthreads();
#pragma unroll
        for (int k = 0; k < BK; k++) {
            float4 a0 = *(const float4*)&Ys[k][tm * 8];
            float4 a1 = *(const float4*)&Ys[k][tm * 8 + 4];
            float4 b0 = *(const float4*)&Ws[k][tn * 8];
            float4 b1 = *(const float4*)&Ws[k][tn * 8 + 4];
            float a[8] = {a0.x, a0.y, a0.z, a0.w, a1.x, a1.y, a1.z, a1.w};
            float bb[8] = {b0.x, b0.y, b0.z, b0.w, b1.x, b1.y, b1.z, b1.w};
#pragma unroll
            for (int i = 0; i < 8; i++)
#pragma unroll
                for (int j = 0; j < 8; j++)
                    acc[i][j] = fmaf(a[i], bb[j], acc[i][j]);
        }
        __syncthreads();
    }

    float pw = prelu[0];
    float bv[8];
#pragma unroll
    for (int j = 0; j < 8; j++) bv[j] = bias[tn * 8 + j];
#pragma unroll
    for (int i = 0; i < 8; i++) {
        int row = m0 + tm * 8 + i;
        if (row < M) {
            float4 o0, o1;
            float v0 = acc[i][0] + bv[0], v1 = acc[i][1] + bv[1];
            float v2 = acc[i][2] + bv[2], v3 = acc[i][3] + bv[3];
            float v4 = acc[i][4] + bv[4], v5 = acc[i][5] + bv[5];
            float v6 = acc[i][6] + bv[6], v7 = acc[i][7] + bv[7];
            o0.x = v0 >= 0.f ? v0 : pw * v0; o0.y = v1 >= 0.f ? v1 : pw * v1;
            o0.z = v2 >= 0.f ? v2 : pw * v2; o0.w = v3 >= 0.f ? v3 : pw * v3;
            o1.x = v4 >= 0.f ? v4 : pw * v4; o1.y = v5 >= 0.f ? v5 : pw * v5;
            o1.z = v6 >= 0.f ? v6 : pw * v6; o1.w = v7 >= 0.f ? v7 : pw * v7;
            *(float4*)&out[(size_t)row * OUT_DIM + tn * 8] = o0;
            *(float4*)&out[(size_t)row * OUT_DIM + tn * 8 + 4] = o1;
        }
    }
}

// ---------------- launch ----------------
extern "C" void kernel_launch(void* const* d_in, const int* in_sizes, int n_in,
                              void* d_out, int out_size) {
    const float* ent  = (const float*)d_in[0];
    const void*  bids = d_in[1];
    const void*  ei   = d_in[2];
    const float* W    = (const float*)d_in[3];
    const float* bias = (const float*)d_in[4];
    const float* wa   = (const float*)d_in[5];
    const float* pw   = (const float*)d_in[6];

    int KG = in_sizes[0] / IN_DIM;
    int B  = in_sizes[1];
    int E  = in_sizes[2] / 2;
    if (KG > KG_MAX) KG = KG_MAX;
    if (B > B_MAX) B = B_MAX;
    if (E > E_MAX) E = E_MAX;

    int nbdr = (KG + 7) / 8;
    int nbsl = (B + 7) / 8;
    int nbh  = (E + 255) / 256;

    k_prep<<<1, 256>>>(bids, W, bias, wa, B);
    k_fused<<<nbdr + nbsl + nbh, 256>>>(ent, bids, ei, KG, B, E, nbdr, nbsl);
    k_scan<<<1, 1024>>>(B);
    k_scatter<<<(E + 255) / 256, 256>>>(ei, E);
    k_agg<<<(B + 7) / 8, 256>>>(ent, ei, E, B);
    k_gemm<<<(B + 127) / 128, 256>>>(bias, pw, (float*)d_out, B);
}

// round 4
// speedup vs baseline: 1.0734x; 1.0734x over previous
#include <cuda_runtime.h>
#include <cuda_fp16.h>
#include <stdint.h>

#define KG_MAX 200000
#define B_MAX  20000
#define E_MAX  640000
#define IN_DIM 256
#define OUT_DIM 128

// ---------------- device scratch ----------------
__device__ int   g_is64;
__device__ __align__(16) float g_vL[IN_DIM];
__device__ __align__(16) float g_vR[IN_DIM];
__device__ float g_cLR;
__device__ float g_dR[KG_MAX];
__device__ float g_sL[B_MAX];
__device__ float g_as[B_MAX];
__device__ int   g_cnt[B_MAX];
__device__ int   g_cur[B_MAX];
__device__ int   g_off[B_MAX + 1];
__device__ int   g_csr[E_MAX];
__device__ int   g_colv[E_MAX];
__device__ float g_attv[E_MAX];
__device__ __align__(16) __half g_enth[(size_t)KG_MAX * IN_DIM];   // fp16 copy of ent
__device__ __align__(16) float g_Wt[IN_DIM * OUT_DIM];
__device__ __align__(16) float g_Y[(size_t)B_MAX * IN_DIM];

__device__ __forceinline__ int ld_row(const void* p, int e, int is64) {
    return is64 ? (int)((const long long*)p)[e] : ((const int*)p)[e];
}
__device__ __forceinline__ int ld_col(const void* p, int E, int e, int is64) {
    return is64 ? (int)((const long long*)p)[(long long)E + e]
                : ((const int*)p)[E + e];
}

// ---------------- k_prep ----------------
__global__ void k_prep(const void* __restrict__ bids,
                       const float* __restrict__ W,
                       const float* __restrict__ bias,
                       const float* __restrict__ wa,
                       int B) {
    int t = threadIdx.x;  // 256
    __shared__ int s_nz;
    if (t == 0) s_nz = 0;
    __syncthreads();
    const unsigned int* u = (const unsigned int*)bids;
    if (u[2 * t + 1] != 0u) atomicOr(&s_nz, 1);
    __syncthreads();
    if (t == 0) g_is64 = s_nz ? 0 : 1;

    float vl = 0.f, vr = 0.f;
#pragma unroll 4
    for (int n = 0; n < OUT_DIM; n++) {
        float w = W[n * IN_DIM + t];
        vl = fmaf(w, wa[n], vl);
        vr = fmaf(w, wa[OUT_DIM + n], vr);
    }
    g_vL[t] = vl;
    g_vR[t] = vr;

    __shared__ float sr[256];
    sr[t] = (t < OUT_DIM) ? bias[t] * (wa[t] + wa[t + OUT_DIM]) : 0.f;
    __syncthreads();
    for (int off = 128; off > 0; off >>= 1) {
        if (t < off) sr[t] += sr[t + off];
        __syncthreads();
    }
    if (t == 0) g_cLR = sr[0];

    for (int idx = t; idx < OUT_DIM * IN_DIM; idx += 256) {
        int k = idx >> 7, n = idx & 127;
        g_Wt[idx] = W[n * IN_DIM + k];
    }
    for (int i = t; i < B; i += 256) { g_cnt[i] = 0; g_cur[i] = 0; }
}

// ---------------- k_fused: dR + fp16 convert, sL, histogram --------
__global__ void __launch_bounds__(256) k_fused(
        const float* __restrict__ ent, const void* __restrict__ bids,
        const void* __restrict__ ei, int KG, int B, int E,
        int nbdr, int nbsl) {
    int bid = blockIdx.x;
    int t = threadIdx.x, w = t >> 5, lane = t & 31;
    if (bid < nbdr) {
        int v = bid * 8 + w;
        if (v < KG) {
            const float* x = ent + (size_t)v * IN_DIM + lane * 8;
            float4 x0 = *(const float4*)x;
            float4 x1 = *(const float4*)(x + 4);
            float4 r0 = *(const float4*)&g_vR[lane * 8];
            float4 r1 = *(const float4*)&g_vR[lane * 8 + 4];
            float d = x0.x * r0.x + x0.y * r0.y + x0.z * r0.z + x0.w * r0.w
                    + x1.x * r1.x + x1.y * r1.y + x1.z * r1.z + x1.w * r1.w;
#pragma unroll
            for (int o = 16; o > 0; o >>= 1)
                d += __shfl_xor_sync(0xffffffffu, d, o);
            if (lane == 0) g_dR[v] = d;
            // fp16 copy (coalesced 16B per lane)
            __half2 h0 = __floats2half2_rn(x0.x, x0.y);
            __half2 h1 = __floats2half2_rn(x0.z, x0.w);
            __half2 h2 = __floats2half2_rn(x1.x, x1.y);
            __half2 h3 = __floats2half2_rn(x1.z, x1.w);
            uint4 q;
            q.x = *(unsigned int*)&h0; q.y = *(unsigned int*)&h1;
            q.z = *(unsigned int*)&h2; q.w = *(unsigned int*)&h3;
            ((uint4*)g_enth)[(size_t)v * 32 + lane] = q;
        }
    } else if (bid < nbdr + nbsl) {
        int r = (bid - nbdr) * 8 + w;
        if (r < B) {
            long long gi = g_is64 ? ((const long long*)bids)[r]
                                  : (long long)((const int*)bids)[r];
            const float* x = ent + gi * (long long)IN_DIM + lane * 8;
            float4 x0 = *(const float4*)x;
            float4 x1 = *(const float4*)(x + 4);
            float4 l0 = *(const float4*)&g_vL[lane * 8];
            float4 l1 = *(const float4*)&g_vL[lane * 8 + 4];
            float d = x0.x * l0.x + x0.y * l0.y + x0.z * l0.z + x0.w * l0.w
                    + x1.x * l1.x + x1.y * l1.y + x1.z * l1.z + x1.w * l1.w;
#pragma unroll
            for (int o = 16; o > 0; o >>= 1)
                d += __shfl_xor_sync(0xffffffffu, d, o);
            if (lane == 0) g_sL[r] = d + g_cLR;
        }
    } else {
        int e = (bid - nbdr - nbsl) * 256 + t;
        if (e < E) {
            int r = ld_row(ei, e, g_is64);
            atomicAdd(&g_cnt[r], 1);
        }
    }
}

// ---------------- k_scan ----------------
__global__ void k_scan(int B) {
    __shared__ int s[1024];
    int t = threadIdx.x;
    int CH = (B + 1023) >> 10;
    int lo = t * CH, hi = min(lo + CH, B);
    int sum = 0;
    for (int i = lo; i < hi; i++) sum += g_cnt[i];
    s[t] = sum;
    __syncthreads();
    for (int off = 1; off < 1024; off <<= 1) {
        int v = (t >= off) ? s[t - off] : 0;
        __syncthreads();
        s[t] += v;
        __syncthreads();
    }
    int run = (t == 0) ? 0 : s[t - 1];
    for (int i = lo; i < hi; i++) { g_off[i] = run; run += g_cnt[i]; }
    if (t == 1023) g_off[B] = s[1023];
}

// ---------------- k_scatter ----------------
__global__ void k_scatter(const void* __restrict__ ei, int E) {
    int e = blockIdx.x * blockDim.x + threadIdx.x;
    if (e >= E) return;
    int r = ld_row(ei, e, g_is64);
    int pos = atomicAdd(&g_cur[r], 1);
    g_csr[g_off[r] + pos] = e;
}

// ---------------- k_sortatt: per-row sort + att precompute ----------------
// Warp per row. Bitonic-sort edge ids (deterministic order), then write
// cols + att into flat arrays and the (fixed-pattern) att row-sum.
__global__ void __launch_bounds__(256) k_sortatt(const void* __restrict__ ei,
                                                 int E, int B) {
    __shared__ int s_e[8][128];
    int t = threadIdx.x, w = t >> 5, lane = t & 31;
    int r = blockIdx.x * 8 + w;
    if (r >= B) return;
    int is64 = g_is64;
    int off0 = g_off[r];
    int deg = g_off[r + 1] - off0;
    float base = g_sL[r];

    if (deg <= 128) {
        int P = 1;
        while (P < deg) P <<= 1;
        for (int i = lane; i < P; i += 32)
            s_e[w][i] = (i < deg) ? g_csr[off0 + i] : 0x7fffffff;
        __syncwarp();
        for (int k = 2; k <= P; k <<= 1) {
            for (int j = k >> 1; j > 0; j >>= 1) {
                for (int i = lane; i < P; i += 32) {
                    int ixj = i ^ j;
                    if (ixj > i) {
                        int a = s_e[w][i], c = s_e[w][ixj];
                        bool up = ((i & k) == 0);
                        if ((a > c) == up) { s_e[w][i] = c; s_e[w][ixj] = a; }
                    }
                }
                __syncwarp();
            }
        }
        float ap = 0.f;
        for (int i = lane; i < deg; i += 32) {
            int e = s_e[w][i];
            int c = ld_col(ei, E, e, is64);
            float s = base + g_dR[c];
            float v = s >= 0.f ? s : 0.2f * s;
            float a = __expf(-v);
            g_colv[off0 + i] = c;
            g_attv[off0 + i] = a;
            ap += a;
        }
#pragma unroll
        for (int o = 16; o > 0; o >>= 1)
            ap += __shfl_down_sync(0xffffffffu, ap, o);
        if (lane == 0) g_as[r] = ap;
    } else {
        // deterministic fallback (increasing edge-id selection)
        int last = -1;
        float asum = 0.f;
        for (int rk = 0; rk < deg; rk++) {
            int m = 0x7fffffff;
            for (int i = lane; i < deg; i += 32) {
                int ec = g_csr[off0 + i];
                if (ec > last && ec < m) m = ec;
            }
#pragma unroll
            for (int o = 16; o > 0; o >>= 1)
                m = min(m, __shfl_xor_sync(0xffffffffu, m, o));
            int c = ld_col(ei, E, m, is64);
            float s = base + g_dR[c];
            float v = s >= 0.f ? s : 0.2f * s;
            float a = __expf(-v);
            if (lane == 0) { g_colv[off0 + rk] = c; g_attv[off0 + rk] = a; }
            asum += a;
            last = m;
        }
        if (lane == 0) g_as[r] = asum;
    }
}

// ---------------- k_agg: warp per row, fp16 gather stream ----------------
__global__ void __launch_bounds__(256) k_agg(int B) {
    int t = threadIdx.x, w = t >> 5, lane = t & 31;
    int r = blockIdx.x * 8 + w;
    if (r >= B) return;
    int off0 = g_off[r];
    int deg = g_off[r + 1] - off0;

    const uint4* eh = (const uint4*)g_enth;  // 32 uint4 per row
    float4 A0 = make_float4(0.f, 0.f, 0.f, 0.f);
    float4 A1 = make_float4(0.f, 0.f, 0.f, 0.f);

    int i = 0;
    for (; i + 4 <= deg; i += 4) {
        int c0 = g_colv[off0 + i],     c1 = g_colv[off0 + i + 1];
        int c2 = g_colv[off0 + i + 2], c3 = g_colv[off0 + i + 3];
        float a0 = g_attv[off0 + i],     a1 = g_attv[off0 + i + 1];
        float a2 = g_attv[off0 + i + 2], a3 = g_attv[off0 + i + 3];
        uint4 q0 = __ldg(&eh[(size_t)c0 * 32 + lane]);
        uint4 q1 = __ldg(&eh[(size_t)c1 * 32 + lane]);
        uint4 q2 = __ldg(&eh[(size_t)c2 * 32 + lane]);
        uint4 q3 = __ldg(&eh[(size_t)c3 * 32 + lane]);
#define ACC(q, a) do { \
        float2 f0 = __half22float2(*(__half2*)&(q).x); \
        float2 f1 = __half22float2(*(__half2*)&(q).y); \
        float2 f2 = __half22float2(*(__half2*)&(q).z); \
        float2 f3 = __half22float2(*(__half2*)&(q).w); \
        A0.x = fmaf((a), f0.x, A0.x); A0.y = fmaf((a), f0.y, A0.y); \
        A0.z = fmaf((a), f1.x, A0.z); A0.w = fmaf((a), f1.y, A0.w); \
        A1.x = fmaf((a), f2.x, A1.x); A1.y = fmaf((a), f2.y, A1.y); \
        A1.z = fmaf((a), f3.x, A1.z); A1.w = fmaf((a), f3.y, A1.w); \
    } while (0)
        ACC(q0, a0); ACC(q1, a1); ACC(q2, a2); ACC(q3, a3);
    }
    for (; i < deg; i++) {
        int c = g_colv[off0 + i];
        float a = g_attv[off0 + i];
        uint4 q = __ldg(&eh[(size_t)c * 32 + lane]);
        ACC(q, a);
    }
#undef ACC

    float inv = 1.0f / g_as[r];
    float* y = &g_Y[(size_t)r * IN_DIM + lane * 8];
    float4 o0, o1;
    o0.x = A0.x * inv; o0.y = A0.y * inv; o0.z = A0.z * inv; o0.w = A0.w * inv;
    o1.x = A1.x * inv; o1.y = A1.y * inv; o1.z = A1.z * inv; o1.w = A1.w * inv;
    *(float4*)y = o0;
    *(float4*)(y + 4) = o1;
}

// ---------------- k_gemm ----------------
__global__ void __launch_bounds__(256) k_gemm(const float* __restrict__ bias,
                                              const float* __restrict__ prelu,
                                              float* __restrict__ out, int M) {
    const int BK = 16;
    __shared__ __align__(16) float Ys[BK][128];
    __shared__ __align__(16) float Ws[BK][128];

    int tid = threadIdx.x;
    int m0 = blockIdx.x * 128;
    int tm = tid >> 4;
    int tn = tid & 15;

    float acc[8][8];
#pragma unroll
    for (int i = 0; i < 8; i++)
#pragma unroll
        for (int j = 0; j < 8; j++) acc[i][j] = 0.f;

    for (int kt = 0; kt < IN_DIM; kt += BK) {
#pragma unroll
        for (int i = 0; i < 2; i++) {
            int f = tid * 2 + i;
            int mr = f >> 2;
            int kc = (f & 3) << 2;
            float4 v = make_float4(0.f, 0.f, 0.f, 0.f);
            int row = m0 + mr;
            if (row < M) v = *(const float4*)&g_Y[(size_t)row * IN_DIM + kt + kc];
            Ys[kc + 0][mr] = v.x; Ys[kc + 1][mr] = v.y;
            Ys[kc + 2][mr] = v.z; Ys[kc + 3][mr] = v.w;
        }
#pragma unroll
        for (int i = 0; i < 2; i++) {
            int idx = tid + i * 256;
            int kr = idx >> 5;
            int nc = (idx & 31) << 2;
            *(float4*)&Ws[kr][nc] = *(const float4*)&g_Wt[(kt + kr) * OUT_DIM + nc];
        }
        __syncthreads();
#pragma unroll
        for (int k = 0; k < BK; k++) {
            float4 a0 = *(const float4*)&Ys[k][tm * 8];
            float4 a1 = *(const float4*)&Ys[k][tm * 8 + 4];
            float4 b0 = *(const float4*)&Ws[k][tn * 8];
            float4 b1 = *(const float4*)&Ws[k][tn * 8 + 4];
            float a[8] = {a0.x, a0.y, a0.z, a0.w, a1.x, a1.y, a1.z, a1.w};
            float bb[8] = {b0.x, b0.y, b0.z, b0.w, b1.x, b1.y, b1.z, b1.w};
#pragma unroll
            for (int i = 0; i < 8; i++)
#pragma unroll
                for (int j = 0; j < 8; j++)
                    acc[i][j] = fmaf(a[i], bb[j], acc[i][j]);
        }
        __syncthreads();
    }

    float pw = prelu[0];
    float bv[8];
#pragma unroll
    for (int j = 0; j < 8; j++) bv[j] = bias[tn * 8 + j];
#pragma unroll
    for (int i = 0; i < 8; i++) {
        int row = m0 + tm * 8 + i;
        if (row < M) {
            float4 o0, o1;
            float v0 = acc[i][0] + bv[0], v1 = acc[i][1] + bv[1];
            float v2 = acc[i][2] + bv[2], v3 = acc[i][3] + bv[3];
            float v4 = acc[i][4] + bv[4], v5 = acc[i][5] + bv[5];
            float v6 = acc[i][6] + bv[6], v7 = acc[i][7] + bv[7];
            o0.x = v0 >= 0.f ? v0 : pw * v0; o0.y = v1 >= 0.f ? v1 : pw * v1;
            o0.z = v2 >= 0.f ? v2 : pw * v2; o0.w = v3 >= 0.f ? v3 : pw * v3;
            o1.x = v4 >= 0.f ? v4 : pw * v4; o1.y = v5 >= 0.f ? v5 : pw * v5;
            o1.z = v6 >= 0.f ? v6 : pw * v6; o1.w = v7 >= 0.f ? v7 : pw * v7;
            *(float4*)&out[(size_t)row * OUT_DIM + tn * 8] = o0;
            *(float4*)&out[(size_t)row * OUT_DIM + tn * 8 + 4] = o1;
        }
    }
}

// ---------------- launch ----------------
extern "C" void kernel_launch(void* const* d_in, const int* in_sizes, int n_in,
                              void* d_out, int out_size) {
    const float* ent  = (const float*)d_in[0];
    const void*  bids = d_in[1];
    const void*  ei   = d_in[2];
    const float* W    = (const float*)d_in[3];
    const float* bias = (const float*)d_in[4];
    const float* wa   = (const float*)d_in[5];
    const float* pw   = (const float*)d_in[6];

    int KG = in_sizes[0] / IN_DIM;
    int B  = in_sizes[1];
    int E  = in_sizes[2] / 2;
    if (KG > KG_MAX) KG = KG_MAX;
    if (B > B_MAX) B = B_MAX;
    if (E > E_MAX) E = E_MAX;

    int nbdr = (KG + 7) / 8;
    int nbsl = (B + 7) / 8;
    int nbh  = (E + 255) / 256;

    k_prep<<<1, 256>>>(bids, W, bias, wa, B);
    k_fused<<<nbdr + nbsl + nbh, 256>>>(ent, bids, ei, KG, B, E, nbdr, nbsl);
    k_scan<<<1, 1024>>>(B);
    k_scatter<<<(E + 255) / 256, 256>>>(ei, E);
    k_sortatt<<<(B + 7) / 8, 256>>>(ei, E, B);
    k_agg<<<(B + 7) / 8, 256>>>(B);
    k_gemm<<<(B + 127) / 128, 256>>>(bias, pw, (float*)d_out, B);
}

// round 5
// speedup vs baseline: 1.1764x; 1.0960x over previous
#include <cuda_runtime.h>
#include <cuda_fp16.h>
#include <stdint.h>

#define KG_MAX 200000
#define B_MAX  20000
#define E_MAX  640000
#define IN_DIM 256
#define OUT_DIM 128

// ---------------- device scratch ----------------
__device__ int   g_is64;
__device__ __align__(16) float g_vL[IN_DIM];
__device__ __align__(16) float g_vR[IN_DIM];
__device__ float g_cLR;
__device__ float g_dR[KG_MAX];
__device__ float g_sL[B_MAX];
__device__ int   g_cnt[B_MAX];
__device__ int   g_cur[B_MAX];
__device__ int   g_off[B_MAX + 1];
__device__ int   g_csr[E_MAX];
__device__ __align__(16) __half g_enth[(size_t)KG_MAX * IN_DIM];
__device__ __align__(16) float g_Wt[IN_DIM * OUT_DIM];
__device__ __align__(16) float g_Y[(size_t)B_MAX * IN_DIM];

__device__ __forceinline__ int ld_row(const void* p, int e, int is64) {
    return is64 ? (int)((const long long*)p)[e] : ((const int*)p)[e];
}
__device__ __forceinline__ int ld_col(const void* p, int E, int e, int is64) {
    return is64 ? (int)((const long long*)p)[(long long)E + e]
                : ((const int*)p)[E + e];
}

// ---------------- k_prep ----------------
__global__ void k_prep(const void* __restrict__ bids,
                       const float* __restrict__ W,
                       const float* __restrict__ bias,
                       const float* __restrict__ wa,
                       int B) {
    int t = threadIdx.x;  // 256
    __shared__ int s_nz;
    if (t == 0) s_nz = 0;
    __syncthreads();
    const unsigned int* u = (const unsigned int*)bids;
    if (u[2 * t + 1] != 0u) atomicOr(&s_nz, 1);
    __syncthreads();
    if (t == 0) g_is64 = s_nz ? 0 : 1;

    float vl = 0.f, vr = 0.f;
#pragma unroll 4
    for (int n = 0; n < OUT_DIM; n++) {
        float w = W[n * IN_DIM + t];
        vl = fmaf(w, wa[n], vl);
        vr = fmaf(w, wa[OUT_DIM + n], vr);
    }
    g_vL[t] = vl;
    g_vR[t] = vr;

    __shared__ float sr[256];
    sr[t] = (t < OUT_DIM) ? bias[t] * (wa[t] + wa[t + OUT_DIM]) : 0.f;
    __syncthreads();
    for (int off = 128; off > 0; off >>= 1) {
        if (t < off) sr[t] += sr[t + off];
        __syncthreads();
    }
    if (t == 0) g_cLR = sr[0];

    for (int idx = t; idx < OUT_DIM * IN_DIM; idx += 256) {
        int k = idx >> 7, n = idx & 127;
        g_Wt[idx] = W[n * IN_DIM + k];
    }
    for (int i = t; i < B; i += 256) { g_cnt[i] = 0; g_cur[i] = 0; }
}

// ---------------- k_fused: dR + fp16 convert + sL (stream A) --------
__global__ void __launch_bounds__(256) k_fused(
        const float* __restrict__ ent, const void* __restrict__ bids,
        int KG, int B, int nbdr) {
    int bid = blockIdx.x;
    int t = threadIdx.x, w = t >> 5, lane = t & 31;
    if (bid < nbdr) {
        int v = bid * 8 + w;
        if (v < KG) {
            const float* x = ent + (size_t)v * IN_DIM + lane * 8;
            float4 x0 = *(const float4*)x;
            float4 x1 = *(const float4*)(x + 4);
            float4 r0 = *(const float4*)&g_vR[lane * 8];
            float4 r1 = *(const float4*)&g_vR[lane * 8 + 4];
            float d = x0.x * r0.x + x0.y * r0.y + x0.z * r0.z + x0.w * r0.w
                    + x1.x * r1.x + x1.y * r1.y + x1.z * r1.z + x1.w * r1.w;
#pragma unroll
            for (int o = 16; o > 0; o >>= 1)
                d += __shfl_xor_sync(0xffffffffu, d, o);
            if (lane == 0) g_dR[v] = d;
            __half2 h0 = __floats2half2_rn(x0.x, x0.y);
            __half2 h1 = __floats2half2_rn(x0.z, x0.w);
            __half2 h2 = __floats2half2_rn(x1.x, x1.y);
            __half2 h3 = __floats2half2_rn(x1.z, x1.w);
            uint4 q;
            q.x = *(unsigned int*)&h0; q.y = *(unsigned int*)&h1;
            q.z = *(unsigned int*)&h2; q.w = *(unsigned int*)&h3;
            ((uint4*)g_enth)[(size_t)v * 32 + lane] = q;
        }
    } else {
        int r = (bid - nbdr) * 8 + w;
        if (r < B) {
            long long gi = g_is64 ? ((const long long*)bids)[r]
                                  : (long long)((const int*)bids)[r];
            const float* x = ent + gi * (long long)IN_DIM + lane * 8;
            float4 x0 = *(const float4*)x;
            float4 x1 = *(const float4*)(x + 4);
            float4 l0 = *(const float4*)&g_vL[lane * 8];
            float4 l1 = *(const float4*)&g_vL[lane * 8 + 4];
            float d = x0.x * l0.x + x0.y * l0.y + x0.z * l0.z + x0.w * l0.w
                    + x1.x * l1.x + x1.y * l1.y + x1.z * l1.z + x1.w * l1.w;
#pragma unroll
            for (int o = 16; o > 0; o >>= 1)
                d += __shfl_xor_sync(0xffffffffu, d, o);
            if (lane == 0) g_sL[r] = d + g_cLR;
        }
    }
}

// ---------------- k_hist (stream B) ----------------
__global__ void k_hist(const void* __restrict__ ei, int E) {
    int e = blockIdx.x * blockDim.x + threadIdx.x;
    if (e >= E) return;
    int r = ld_row(ei, e, g_is64);
    atomicAdd(&g_cnt[r], 1);
}

// ---------------- k_scan (stream B) ----------------
__global__ void k_scan(int B) {
    __shared__ int s[1024];
    int t = threadIdx.x;
    int CH = (B + 1023) >> 10;
    int lo = t * CH, hi = min(lo + CH, B);
    int sum = 0;
    for (int i = lo; i < hi; i++) sum += g_cnt[i];
    s[t] = sum;
    __syncthreads();
    for (int off = 1; off < 1024; off <<= 1) {
        int v = (t >= off) ? s[t - off] : 0;
        __syncthreads();
        s[t] += v;
        __syncthreads();
    }
    int run = (t == 0) ? 0 : s[t - 1];
    for (int i = lo; i < hi; i++) { g_off[i] = run; run += g_cnt[i]; }
    if (t == 1023) g_off[B] = s[1023];
}

// ---------------- k_scatter (stream B) ----------------
__global__ void k_scatter(const void* __restrict__ ei, int E) {
    int e = blockIdx.x * blockDim.x + threadIdx.x;
    if (e >= E) return;
    int r = ld_row(ei, e, g_is64);
    int pos = atomicAdd(&g_cur[r], 1);
    g_csr[g_off[r] + pos] = e;
}

// ---------------- k_agg: sort + att + fp16 gather, warp per row ------------
__global__ void __launch_bounds__(256) k_agg(const void* __restrict__ ei,
                                             int E, int B) {
    __shared__ int   s_e[8][128];
    __shared__ float s_a[8][128];
    int t = threadIdx.x, w = t >> 5, lane = t & 31;
    int r = blockIdx.x * 8 + w;
    if (r >= B) return;
    int is64 = g_is64;
    int off0 = g_off[r];
    int deg = g_off[r + 1] - off0;
    float base = g_sL[r];

    const uint4* eh = (const uint4*)g_enth;  // 32 uint4 per row
    float4 A0 = make_float4(0.f, 0.f, 0.f, 0.f);
    float4 A1 = make_float4(0.f, 0.f, 0.f, 0.f);
    float asum = 0.f;

#define ACC(q, a) do { \
        float2 f0 = __half22float2(*(__half2*)&(q).x); \
        float2 f1 = __half22float2(*(__half2*)&(q).y); \
        float2 f2 = __half22float2(*(__half2*)&(q).z); \
        float2 f3 = __half22float2(*(__half2*)&(q).w); \
        A0.x = fmaf((a), f0.x, A0.x); A0.y = fmaf((a), f0.y, A0.y); \
        A0.z = fmaf((a), f1.x, A0.z); A0.w = fmaf((a), f1.y, A0.w); \
        A1.x = fmaf((a), f2.x, A1.x); A1.y = fmaf((a), f2.y, A1.y); \
        A1.z = fmaf((a), f3.x, A1.z); A1.w = fmaf((a), f3.y, A1.w); \
    } while (0)

    if (deg <= 128) {
        int P = 1;
        while (P < deg) P <<= 1;
        for (int i = lane; i < P; i += 32)
            s_e[w][i] = (i < deg) ? g_csr[off0 + i] : 0x7fffffff;
        __syncwarp();
        for (int k = 2; k <= P; k <<= 1) {
            for (int j = k >> 1; j > 0; j >>= 1) {
                for (int i = lane; i < P; i += 32) {
                    int ixj = i ^ j;
                    if (ixj > i) {
                        int a = s_e[w][i], c = s_e[w][ixj];
                        bool up = ((i & k) == 0);
                        if ((a > c) == up) { s_e[w][i] = c; s_e[w][ixj] = a; }
                    }
                }
                __syncwarp();
            }
        }
        // col + att (overwrite s_e with cols); lane-strided order is fixed
        float ap = 0.f;
        for (int i = lane; i < deg; i += 32) {
            int e = s_e[w][i];
            int c = ld_col(ei, E, e, is64);
            float s = base + g_dR[c];
            float v = s >= 0.f ? s : 0.2f * s;
            float a = __expf(-v);
            s_e[w][i] = c;
            s_a[w][i] = a;
            ap += a;
        }
#pragma unroll
        for (int o = 16; o > 0; o >>= 1)
            ap += __shfl_xor_sync(0xffffffffu, ap, o);
        asum = ap;
        __syncwarp();

        int i = 0;
        for (; i + 4 <= deg; i += 4) {
            int c0 = s_e[w][i],     c1 = s_e[w][i + 1];
            int c2 = s_e[w][i + 2], c3 = s_e[w][i + 3];
            float a0 = s_a[w][i],     a1 = s_a[w][i + 1];
            float a2 = s_a[w][i + 2], a3 = s_a[w][i + 3];
            uint4 q0 = __ldg(&eh[(size_t)c0 * 32 + lane]);
            uint4 q1 = __ldg(&eh[(size_t)c1 * 32 + lane]);
            uint4 q2 = __ldg(&eh[(size_t)c2 * 32 + lane]);
            uint4 q3 = __ldg(&eh[(size_t)c3 * 32 + lane]);
            ACC(q0, a0); ACC(q1, a1); ACC(q2, a2); ACC(q3, a3);
        }
        for (; i < deg; i++) {
            int c = s_e[w][i];
            float a = s_a[w][i];
            uint4 q = __ldg(&eh[(size_t)c * 32 + lane]);
            ACC(q, a);
        }
    } else {
        // deterministic fallback: increasing edge-id selection (rare)
        int last = -1;
        for (int rk = 0; rk < deg; rk++) {
            int m = 0x7fffffff;
            for (int i = lane; i < deg; i += 32) {
                int ec = g_csr[off0 + i];
                if (ec > last && ec < m) m = ec;
            }
#pragma unroll
            for (int o = 16; o > 0; o >>= 1)
                m = min(m, __shfl_xor_sync(0xffffffffu, m, o));
            int c = ld_col(ei, E, m, is64);
            float s = base + g_dR[c];
            float v = s >= 0.f ? s : 0.2f * s;
            float a = __expf(-v);
            uint4 q = __ldg(&eh[(size_t)c * 32 + lane]);
            asum += a;
            ACC(q, a);
            last = m;
        }
    }
#undef ACC

    float inv = 1.0f / asum;
    float* y = &g_Y[(size_t)r * IN_DIM + lane * 8];
    float4 o0, o1;
    o0.x = A0.x * inv; o0.y = A0.y * inv; o0.z = A0.z * inv; o0.w = A0.w * inv;
    o1.x = A1.x * inv; o1.y = A1.y * inv; o1.z = A1.z * inv; o1.w = A1.w * inv;
    *(float4*)y = o0;
    *(float4*)(y + 4) = o1;
}

// ---------------- k_gemm: 32x128 tile, micro 4x4 (625 blocks, low quant) ---
__global__ void __launch_bounds__(256) k_gemm(const float* __restrict__ bias,
                                              const float* __restrict__ prelu,
                                              float* __restrict__ out, int M) {
    const int BK = 16, BM = 32;
    __shared__ __align__(16) float Ys[BK][BM];
    __shared__ __align__(16) float Ws[BK][128];

    int tid = threadIdx.x;
    int m0 = blockIdx.x * BM;
    int tm = tid >> 5;    // 0..7 -> 4 rows each
    int tn = tid & 31;    // 0..31 -> 4 cols each

    float acc[4][4];
#pragma unroll
    for (int i = 0; i < 4; i++)
#pragma unroll
        for (int j = 0; j < 4; j++) acc[i][j] = 0.f;

    for (int kt = 0; kt < IN_DIM; kt += BK) {
        // stage Y tile: 32 rows x 16 k -> Ys[k][m] (threads 0..127)
        if (tid < 128) {
            int mr = tid >> 2;
            int kc = (tid & 3) << 2;
            float4 v = make_float4(0.f, 0.f, 0.f, 0.f);
            int row = m0 + mr;
            if (row < M) v = *(const float4*)&g_Y[(size_t)row * IN_DIM + kt + kc];
            Ys[kc + 0][mr] = v.x; Ys[kc + 1][mr] = v.y;
            Ys[kc + 2][mr] = v.z; Ys[kc + 3][mr] = v.w;
        }
        // stage Wt tile: 16 k x 128 n
#pragma unroll
        for (int i = 0; i < 2; i++) {
            int idx = tid + i * 256;
            int kr = idx >> 5;
            int nc = (idx & 31) << 2;
            *(float4*)&Ws[kr][nc] = *(const float4*)&g_Wt[(kt + kr) * OUT_DIM + nc];
        }
        __syncthreads();
#pragma unroll
        for (int k = 0; k < BK; k++) {
            float4 av = *(const float4*)&Ys[k][tm * 4];
            float4 bv = *(const float4*)&Ws[k][tn * 4];
            float a[4] = {av.x, av.y, av.z, av.w};
            float bb[4] = {bv.x, bv.y, bv.z, bv.w};
#pragma unroll
            for (int i = 0; i < 4; i++)
#pragma unroll
                for (int j = 0; j < 4; j++)
                    acc[i][j] = fmaf(a[i], bb[j], acc[i][j]);
        }
        __syncthreads();
    }

    float pw = prelu[0];
    float4 bv4 = *(const float4*)&bias[tn * 4];
    float bv[4] = {bv4.x, bv4.y, bv4.z, bv4.w};
#pragma unroll
    for (int i = 0; i < 4; i++) {
        int row = m0 + tm * 4 + i;
        if (row < M) {
            float4 o;
            float v0 = acc[i][0] + bv[0], v1 = acc[i][1] + bv[1];
            float v2 = acc[i][2] + bv[2], v3 = acc[i][3] + bv[3];
            o.x = v0 >= 0.f ? v0 : pw * v0;
            o.y = v1 >= 0.f ? v1 : pw * v1;
            o.z = v2 >= 0.f ? v2 : pw * v2;
            o.w = v3 >= 0.f ? v3 : pw * v3;
            *(float4*)&out[(size_t)row * OUT_DIM + tn * 4] = o;
        }
    }
}

// ---------------- launch: fork CSR chain onto a second captured stream -----
extern "C" void kernel_launch(void* const* d_in, const int* in_sizes, int n_in,
                              void* d_out, int out_size) {
    const float* ent  = (const float*)d_in[0];
    const void*  bids = d_in[1];
    const void*  ei   = d_in[2];
    const float* W    = (const float*)d_in[3];
    const float* bias = (const float*)d_in[4];
    const float* wa   = (const float*)d_in[5];
    const float* pw   = (const float*)d_in[6];

    int KG = in_sizes[0] / IN_DIM;
    int B  = in_sizes[1];
    int E  = in_sizes[2] / 2;
    if (KG > KG_MAX) KG = KG_MAX;
    if (B > B_MAX) B = B_MAX;
    if (E > E_MAX) E = E_MAX;

    int nbdr = (KG + 7) / 8;
    int nbsl = (B + 7) / 8;

    cudaStream_t s2;
    cudaEvent_t ev1, ev2;
    cudaStreamCreateWithFlags(&s2, cudaStreamNonBlocking);
    cudaEventCreateWithFlags(&ev1, cudaEventDisableTiming);
    cudaEventCreateWithFlags(&ev2, cudaEventDisableTiming);

    k_prep<<<1, 256>>>(bids, W, bias, wa, B);
    cudaEventRecord(ev1, 0);
    cudaStreamWaitEvent(s2, ev1, 0);

    // stream B: CSR chain (atomic/latency-bound)
    k_hist<<<(E + 255) / 256, 256, 0, s2>>>(ei, E);
    k_scan<<<1, 1024, 0, s2>>>(B);
    k_scatter<<<(E + 255) / 256, 256, 0, s2>>>(ei, E);
    cudaEventRecord(ev2, s2);

    // stream A (default): BW-bound embedding pass, concurrent with CSR chain
    k_fused<<<nbdr + nbsl, 256>>>(ent, bids, KG, B, nbdr);

    cudaStreamWaitEvent(0, ev2, 0);
    k_agg<<<(B + 7) / 8, 256>>>(ei, E, B);
    k_gemm<<<(B + 31) / 32, 256>>>(bias, pw, (float*)d_out, B);

    cudaEventDestroy(ev1);
    cudaEventDestroy(ev2);
    cudaStreamDestroy(s2);
}

// round 6
// speedup vs baseline: 1.5216x; 1.2935x over previous
#include <cuda_runtime.h>
#include <cuda_fp16.h>
#include <stdint.h>

#define KG_MAX 200000
#define B_MAX  20000
#define E_MAX  640000
#define IN_DIM 256
#define OUT_DIM 128

// ---------------- device scratch ----------------
__device__ int   g_is64;
__device__ __align__(16) float g_vL[IN_DIM];
__device__ __align__(16) float g_vR[IN_DIM];
__device__ float g_cLR;
__device__ float g_dR[KG_MAX];
__device__ float g_sL[B_MAX];
__device__ int   g_cnt[B_MAX];
__device__ int   g_cur[B_MAX];
__device__ int   g_off[B_MAX + 1];
__device__ int   g_csr[E_MAX];
__device__ __align__(16) __half g_enth[(size_t)KG_MAX * IN_DIM];
__device__ __align__(16) __half g_Yh[(size_t)B_MAX * IN_DIM];       // fp16 Y
__device__ __align__(16) unsigned g_Wfrag[16 * 16 * 32 * 2];        // mma B frags

__device__ __forceinline__ int ld_row(const void* p, int e, int is64) {
    return is64 ? (int)((const long long*)p)[e] : ((const int*)p)[e];
}
__device__ __forceinline__ int ld_col(const void* p, int E, int e, int is64) {
    return is64 ? (int)((const long long*)p)[(long long)E + e]
                : ((const int*)p)[E + e];
}

// ---------------- k_prep ----------------
__global__ void k_prep(const void* __restrict__ bids,
                       const float* __restrict__ W,
                       const float* __restrict__ bias,
                       const float* __restrict__ wa,
                       int B) {
    int t = threadIdx.x;  // 256
    __shared__ int s_nz;
    if (t == 0) s_nz = 0;
    __syncthreads();
    const unsigned int* u = (const unsigned int*)bids;
    if (u[2 * t + 1] != 0u) atomicOr(&s_nz, 1);
    __syncthreads();
    if (t == 0) g_is64 = s_nz ? 0 : 1;

    float vl = 0.f, vr = 0.f;
#pragma unroll 4
    for (int n = 0; n < OUT_DIM; n++) {
        float w = W[n * IN_DIM + t];
        vl = fmaf(w, wa[n], vl);
        vr = fmaf(w, wa[OUT_DIM + n], vr);
    }
    g_vL[t] = vl;
    g_vR[t] = vr;

    __shared__ float sr[256];
    sr[t] = (t < OUT_DIM) ? bias[t] * (wa[t] + wa[t + OUT_DIM]) : 0.f;
    __syncthreads();
    for (int off = 128; off > 0; off >>= 1) {
        if (t < off) sr[t] += sr[t + off];
        __syncthreads();
    }
    if (t == 0) g_cLR = sr[0];

    // pack W (fp32 [128][256]) into mma.m16n8k16 B-fragment order, fp16.
    // frag index f = ((ks*16 + nf)*32 + lane)*2 + q :
    //   n = nf*8 + lane/4 ; k = ks*16 + (lane%4)*2 + (q ? 8 : 0)
    // value = half2{ W[n][k], W[n][k+1] }
    for (int f = t; f < 16 * 16 * 32 * 2; f += 256) {
        int q = f & 1;
        int lane = (f >> 1) & 31;
        int nf = (f >> 6) & 15;
        int ks = f >> 10;
        int n = nf * 8 + (lane >> 2);
        int k = ks * 16 + (lane & 3) * 2 + (q ? 8 : 0);
        __half2 h = __floats2half2_rn(W[n * IN_DIM + k], W[n * IN_DIM + k + 1]);
        g_Wfrag[f] = *(unsigned*)&h;
    }
    for (int i = t; i < B; i += 256) { g_cnt[i] = 0; g_cur[i] = 0; }
}

// ---------------- k_fused: dR + fp16 convert + sL (stream A) --------
__global__ void __launch_bounds__(256) k_fused(
        const float* __restrict__ ent, const void* __restrict__ bids,
        int KG, int B, int nbdr) {
    int bid = blockIdx.x;
    int t = threadIdx.x, w = t >> 5, lane = t & 31;
    if (bid < nbdr) {
        int v = bid * 8 + w;
        if (v < KG) {
            const float* x = ent + (size_t)v * IN_DIM + lane * 8;
            float4 x0 = *(const float4*)x;
            float4 x1 = *(const float4*)(x + 4);
            float4 r0 = *(const float4*)&g_vR[lane * 8];
            float4 r1 = *(const float4*)&g_vR[lane * 8 + 4];
            float d = x0.x * r0.x + x0.y * r0.y + x0.z * r0.z + x0.w * r0.w
                    + x1.x * r1.x + x1.y * r1.y + x1.z * r1.z + x1.w * r1.w;
#pragma unroll
            for (int o = 16; o > 0; o >>= 1)
                d += __shfl_xor_sync(0xffffffffu, d, o);
            if (lane == 0) g_dR[v] = d;
            __half2 h0 = __floats2half2_rn(x0.x, x0.y);
            __half2 h1 = __floats2half2_rn(x0.z, x0.w);
            __half2 h2 = __floats2half2_rn(x1.x, x1.y);
            __half2 h3 = __floats2half2_rn(x1.z, x1.w);
            uint4 q;
            q.x = *(unsigned int*)&h0; q.y = *(unsigned int*)&h1;
            q.z = *(unsigned int*)&h2; q.w = *(unsigned int*)&h3;
            ((uint4*)g_enth)[(size_t)v * 32 + lane] = q;
        }
    } else {
        int r = (bid - nbdr) * 8 + w;
        if (r < B) {
            long long gi = g_is64 ? ((const long long*)bids)[r]
                                  : (long long)((const int*)bids)[r];
            const float* x = ent + gi * (long long)IN_DIM + lane * 8;
            float4 x0 = *(const float4*)x;
            float4 x1 = *(const float4*)(x + 4);
            float4 l0 = *(const float4*)&g_vL[lane * 8];
            float4 l1 = *(const float4*)&g_vL[lane * 8 + 4];
            float d = x0.x * l0.x + x0.y * l0.y + x0.z * l0.z + x0.w * l0.w
                    + x1.x * l1.x + x1.y * l1.y + x1.z * l1.z + x1.w * l1.w;
#pragma unroll
            for (int o = 16; o > 0; o >>= 1)
                d += __shfl_xor_sync(0xffffffffu, d, o);
            if (lane == 0) g_sL[r] = d + g_cLR;
        }
    }
}

// ---------------- CSR chain (stream B) ----------------
__global__ void k_hist(const void* __restrict__ ei, int E) {
    int e = blockIdx.x * blockDim.x + threadIdx.x;
    if (e >= E) return;
    int r = ld_row(ei, e, g_is64);
    atomicAdd(&g_cnt[r], 1);
}

__global__ void k_scan(int B) {
    __shared__ int s[1024];
    int t = threadIdx.x;
    int CH = (B + 1023) >> 10;
    int lo = t * CH, hi = min(lo + CH, B);
    int sum = 0;
    for (int i = lo; i < hi; i++) sum += g_cnt[i];
    s[t] = sum;
    __syncthreads();
    for (int off = 1; off < 1024; off <<= 1) {
        int v = (t >= off) ? s[t - off] : 0;
        __syncthreads();
        s[t] += v;
        __syncthreads();
    }
    int run = (t == 0) ? 0 : s[t - 1];
    for (int i = lo; i < hi; i++) { g_off[i] = run; run += g_cnt[i]; }
    if (t == 1023) g_off[B] = s[1023];
}

__global__ void k_scatter(const void* __restrict__ ei, int E) {
    int e = blockIdx.x * blockDim.x + threadIdx.x;
    if (e >= E) return;
    int r = ld_row(ei, e, g_is64);
    int pos = atomicAdd(&g_cur[r], 1);
    g_csr[g_off[r] + pos] = e;
}

// ---------------- warp-register bitonic sort of 64 ints (2/lane) -----------
__device__ __forceinline__ void bitonic64(int& v0, int& v1, int lane) {
#pragma unroll
    for (int k = 2; k <= 32; k <<= 1) {
#pragma unroll
        for (int j = k >> 1; j > 0; j >>= 1) {
            bool low = ((lane & j) == 0);
            int x0 = __shfl_xor_sync(0xffffffffu, v0, j);
            bool asc0 = ((lane & k) == 0);      // elem i0 = lane
            v0 = (asc0 == low) ? min(v0, x0) : max(v0, x0);
            int x1 = __shfl_xor_sync(0xffffffffu, v1, j);
            bool asc1 = (k == 32) ? false : asc0;  // elem i1 = 32+lane
            v1 = (asc1 == low) ? min(v1, x1) : max(v1, x1);
        }
    }
    // k = 64: j = 32 crosses registers (same lane), ascending everywhere
    { int mn = min(v0, v1), mx = max(v0, v1); v0 = mn; v1 = mx; }
#pragma unroll
    for (int j = 16; j > 0; j >>= 1) {
        bool low = ((lane & j) == 0);
        int x0 = __shfl_xor_sync(0xffffffffu, v0, j);
        v0 = low ? min(v0, x0) : max(v0, x0);
        int x1 = __shfl_xor_sync(0xffffffffu, v1, j);
        v1 = low ? min(v1, x1) : max(v1, x1);
    }
}

// ---------------- k_agg: register sort + att + fp16 gather, warp per row ---
__global__ void __launch_bounds__(256) k_agg(const void* __restrict__ ei,
                                             int E, int B) {
    __shared__ int   s_e[8][128];
    __shared__ float s_a[8][128];
    int t = threadIdx.x, w = t >> 5, lane = t & 31;
    int r = blockIdx.x * 8 + w;
    if (r >= B) return;
    int is64 = g_is64;
    int off0 = g_off[r];
    int deg = g_off[r + 1] - off0;
    float base = g_sL[r];

    const uint4* eh = (const uint4*)g_enth;
    float4 A0 = make_float4(0.f, 0.f, 0.f, 0.f);
    float4 A1 = make_float4(0.f, 0.f, 0.f, 0.f);
    float asum = 0.f;

#define ACC(q, a) do { \
        float2 f0 = __half22float2(*(__half2*)&(q).x); \
        float2 f1 = __half22float2(*(__half2*)&(q).y); \
        float2 f2 = __half22float2(*(__half2*)&(q).z); \
        float2 f3 = __half22float2(*(__half2*)&(q).w); \
        A0.x = fmaf((a), f0.x, A0.x); A0.y = fmaf((a), f0.y, A0.y); \
        A0.z = fmaf((a), f1.x, A0.z); A0.w = fmaf((a), f1.y, A0.w); \
        A1.x = fmaf((a), f2.x, A1.x); A1.y = fmaf((a), f2.y, A1.y); \
        A1.z = fmaf((a), f3.x, A1.z); A1.w = fmaf((a), f3.y, A1.w); \
    } while (0)

    if (deg <= 64) {
        // register bitonic sort (no smem passes, no syncwarp)
        int v0 = (lane < deg) ? g_csr[off0 + lane] : 0x7fffffff;
        int v1 = (32 + lane < deg) ? g_csr[off0 + 32 + lane] : 0x7fffffff;
        bitonic64(v0, v1, lane);
        float ap = 0.f;
        if (lane < deg) {
            int c = ld_col(ei, E, v0, is64);
            float s = base + g_dR[c];
            float v = s >= 0.f ? s : 0.2f * s;
            float a = __expf(-v);
            s_e[w][lane] = c; s_a[w][lane] = a;
            ap += a;
        }
        if (32 + lane < deg) {
            int c = ld_col(ei, E, v1, is64);
            float s = base + g_dR[c];
            float v = s >= 0.f ? s : 0.2f * s;
            float a = __expf(-v);
            s_e[w][32 + lane] = c; s_a[w][32 + lane] = a;
            ap += a;
        }
#pragma unroll
        for (int o = 16; o > 0; o >>= 1)
            ap += __shfl_xor_sync(0xffffffffu, ap, o);
        asum = ap;
        __syncwarp();

        int i = 0;
        for (; i + 4 <= deg; i += 4) {
            int c0 = s_e[w][i],     c1 = s_e[w][i + 1];
            int c2 = s_e[w][i + 2], c3 = s_e[w][i + 3];
            float a0 = s_a[w][i],     a1 = s_a[w][i + 1];
            float a2 = s_a[w][i + 2], a3 = s_a[w][i + 3];
            uint4 q0 = __ldg(&eh[(size_t)c0 * 32 + lane]);
            uint4 q1 = __ldg(&eh[(size_t)c1 * 32 + lane]);
            uint4 q2 = __ldg(&eh[(size_t)c2 * 32 + lane]);
            uint4 q3 = __ldg(&eh[(size_t)c3 * 32 + lane]);
            ACC(q0, a0); ACC(q1, a1); ACC(q2, a2); ACC(q3, a3);
        }
        for (; i < deg; i++) {
            int c = s_e[w][i];
            float a = s_a[w][i];
            uint4 q = __ldg(&eh[(size_t)c * 32 + lane]);
            ACC(q, a);
        }
    } else if (deg <= 128) {
        int P = 1;
        while (P < deg) P <<= 1;
        for (int i = lane; i < P; i += 32)
            s_e[w][i] = (i < deg) ? g_csr[off0 + i] : 0x7fffffff;
        __syncwarp();
        for (int k = 2; k <= P; k <<= 1) {
            for (int j = k >> 1; j > 0; j >>= 1) {
                for (int i = lane; i < P; i += 32) {
                    int ixj = i ^ j;
                    if (ixj > i) {
                        int a = s_e[w][i], c = s_e[w][ixj];
                        bool up = ((i & k) == 0);
                        if ((a > c) == up) { s_e[w][i] = c; s_e[w][ixj] = a; }
                    }
                }
                __syncwarp();
            }
        }
        float ap = 0.f;
        for (int i = lane; i < deg; i += 32) {
            int e = s_e[w][i];
            int c = ld_col(ei, E, e, is64);
            float s = base + g_dR[c];
            float v = s >= 0.f ? s : 0.2f * s;
            float a = __expf(-v);
            s_e[w][i] = c;
            s_a[w][i] = a;
            ap += a;
        }
#pragma unroll
        for (int o = 16; o > 0; o >>= 1)
            ap += __shfl_xor_sync(0xffffffffu, ap, o);
        asum = ap;
        __syncwarp();
        int i = 0;
        for (; i + 4 <= deg; i += 4) {
            int c0 = s_e[w][i],     c1 = s_e[w][i + 1];
            int c2 = s_e[w][i + 2], c3 = s_e[w][i + 3];
            float a0 = s_a[w][i],     a1 = s_a[w][i + 1];
            float a2 = s_a[w][i + 2], a3 = s_a[w][i + 3];
            uint4 q0 = __ldg(&eh[(size_t)c0 * 32 + lane]);
            uint4 q1 = __ldg(&eh[(size_t)c1 * 32 + lane]);
            uint4 q2 = __ldg(&eh[(size_t)c2 * 32 + lane]);
            uint4 q3 = __ldg(&eh[(size_t)c3 * 32 + lane]);
            ACC(q0, a0); ACC(q1, a1); ACC(q2, a2); ACC(q3, a3);
        }
        for (; i < deg; i++) {
            int c = s_e[w][i];
            float a = s_a[w][i];
            uint4 q = __ldg(&eh[(size_t)c * 32 + lane]);
            ACC(q, a);
        }
    } else {
        // deterministic fallback: increasing edge-id selection (rare)
        int last = -1;
        for (int rk = 0; rk < deg; rk++) {
            int m = 0x7fffffff;
            for (int i = lane; i < deg; i += 32) {
                int ec = g_csr[off0 + i];
                if (ec > last && ec < m) m = ec;
            }
#pragma unroll
            for (int o = 16; o > 0; o >>= 1)
                m = min(m, __shfl_xor_sync(0xffffffffu, m, o));
            int c = ld_col(ei, E, m, is64);
            float s = base + g_dR[c];
            float v = s >= 0.f ? s : 0.2f * s;
            float a = __expf(-v);
            uint4 q = __ldg(&eh[(size_t)c * 32 + lane]);
            asum += a;
            ACC(q, a);
            last = m;
        }
    }
#undef ACC

    float inv = 1.0f / asum;
    __half2 h0 = __floats2half2_rn(A0.x * inv, A0.y * inv);
    __half2 h1 = __floats2half2_rn(A0.z * inv, A0.w * inv);
    __half2 h2 = __floats2half2_rn(A1.x * inv, A1.y * inv);
    __half2 h3 = __floats2half2_rn(A1.z * inv, A1.w * inv);
    uint4 q;
    q.x = *(unsigned*)&h0; q.y = *(unsigned*)&h1;
    q.z = *(unsigned*)&h2; q.w = *(unsigned*)&h3;
    ((uint4*)g_Yh)[(size_t)r * 32 + lane] = q;
}

// ---------------- k_gemm: HMMA m16n8k16, fp16 in / fp32 acc ----------------
// Block = 256 thr = 8 warps; warp handles 16 rows x 128 cols. B frags come
// pre-packed (g_Wfrag) so every B load is a coalesced LDG.64 from L2.
__global__ void __launch_bounds__(256) k_gemm(const float* __restrict__ bias,
                                              const float* __restrict__ prelu,
                                              float* __restrict__ out, int M) {
    int tid = threadIdx.x;
    int wid = tid >> 5, lane = tid & 31;
    int gid = lane >> 2, tig = lane & 3;
    int mbase = blockIdx.x * 128 + wid * 16;
    int r0 = mbase + gid, r1 = r0 + 8;
    bool p0 = r0 < M, p1 = r1 < M;

    float acc[16][4];
#pragma unroll
    for (int nf = 0; nf < 16; nf++)
#pragma unroll
        for (int j = 0; j < 4; j++) acc[nf][j] = 0.f;

    const __half* Yh = g_Yh;
    const uint2* Wf = (const uint2*)g_Wfrag;

    for (int ks = 0; ks < 16; ks++) {
        int k0 = ks * 16 + tig * 2;
        unsigned a0 = p0 ? *(const unsigned*)&Yh[(size_t)r0 * IN_DIM + k0] : 0u;
        unsigned a1 = p1 ? *(const unsigned*)&Yh[(size_t)r1 * IN_DIM + k0] : 0u;
        unsigned a2 = p0 ? *(const unsigned*)&Yh[(size_t)r0 * IN_DIM + k0 + 8] : 0u;
        unsigned a3 = p1 ? *(const unsigned*)&Yh[(size_t)r1 * IN_DIM + k0 + 8] : 0u;
#pragma unroll
        for (int nf = 0; nf < 16; nf++) {
            uint2 bb = __ldg(&Wf[(ks * 16 + nf) * 32 + lane]);
            asm volatile(
                "mma.sync.aligned.m16n8k16.row.col.f32.f16.f16.f32 "
                "{%0,%1,%2,%3}, {%4,%5,%6,%7}, {%8,%9}, {%0,%1,%2,%3};"
                : "+f"(acc[nf][0]), "+f"(acc[nf][1]),
                  "+f"(acc[nf][2]), "+f"(acc[nf][3])
                : "r"(a0), "r"(a1), "r"(a2), "r"(a3),
                  "r"(bb.x), "r"(bb.y));
        }
    }

    float pw = prelu[0];
#pragma unroll
    for (int nf = 0; nf < 16; nf++) {
        int n0 = nf * 8 + tig * 2;
        float bv0 = __ldg(&bias[n0]), bv1 = __ldg(&bias[n0 + 1]);
        if (p0) {
            float v0 = acc[nf][0] + bv0, v1 = acc[nf][1] + bv1;
            float2 o;
            o.x = v0 >= 0.f ? v0 : pw * v0;
            o.y = v1 >= 0.f ? v1 : pw * v1;
            *(float2*)&out[(size_t)r0 * OUT_DIM + n0] = o;
        }
        if (p1) {
            float v2 = acc[nf][2] + bv0, v3 = acc[nf][3] + bv1;
            float2 o;
            o.x = v2 >= 0.f ? v2 : pw * v2;
            o.y = v3 >= 0.f ? v3 : pw * v3;
            *(float2*)&out[(size_t)r1 * OUT_DIM + n0] = o;
        }
    }
}

// ---------------- launch ----------------
extern "C" void kernel_launch(void* const* d_in, const int* in_sizes, int n_in,
                              void* d_out, int out_size) {
    const float* ent  = (const float*)d_in[0];
    const void*  bids = d_in[1];
    const void*  ei   = d_in[2];
    const float* W    = (const float*)d_in[3];
    const float* bias = (const float*)d_in[4];
    const float* wa   = (const float*)d_in[5];
    const float* pw   = (const float*)d_in[6];

    int KG = in_sizes[0] / IN_DIM;
    int B  = in_sizes[1];
    int E  = in_sizes[2] / 2;
    if (KG > KG_MAX) KG = KG_MAX;
    if (B > B_MAX) B = B_MAX;
    if (E > E_MAX) E = E_MAX;

    int nbdr = (KG + 7) / 8;
    int nbsl = (B + 7) / 8;

    cudaStream_t s2;
    cudaEvent_t ev1, ev2;
    cudaStreamCreateWithFlags(&s2, cudaStreamNonBlocking);
    cudaEventCreateWithFlags(&ev1, cudaEventDisableTiming);
    cudaEventCreateWithFlags(&ev2, cudaEventDisableTiming);

    k_prep<<<1, 256>>>(bids, W, bias, wa, B);
    cudaEventRecord(ev1, 0);
    cudaStreamWaitEvent(s2, ev1, 0);

    // stream B: CSR chain (atomic/latency-bound)
    k_hist<<<(E + 255) / 256, 256, 0, s2>>>(ei, E);
    k_scan<<<1, 1024, 0, s2>>>(B);
    k_scatter<<<(E + 255) / 256, 256, 0, s2>>>(ei, E);
    cudaEventRecord(ev2, s2);

    // stream A (default): BW-bound embedding pass, concurrent with CSR chain
    k_fused<<<nbdr + nbsl, 256>>>(ent, bids, KG, B, nbdr);

    cudaStreamWaitEvent(0, ev2, 0);
    k_agg<<<(B + 7) / 8, 256>>>(ei, E, B);
    k_gemm<<<(B + 127) / 128, 256>>>(bias, pw, (float*)d_out, B);

    cudaEventDestroy(ev1);
    cudaEventDestroy(ev2);
    cudaStreamDestroy(s2);
}